// round 3
// baseline (speedup 1.0000x reference)
#include <cuda_runtime.h>
#include <cuda_bf16.h>
#include <stdint.h>

// ---------------------------------------------------------------------------
// Problem constants
// ---------------------------------------------------------------------------
#define QDIM   4096
#define NDIM   8192
#define DDIM   256
#define KSPLIT 768          // split-bf16 K: A=[hi|hi|lo], B=[hi|lo|hi]
#define BM     128
#define BN     128
#define BK     64
#define NKT    12           // 768/64
#define STAGES 4
#define NITER  10

// ---------------------------------------------------------------------------
// Device scratch (no allocation allowed)
// ---------------------------------------------------------------------------
__device__ __align__(128) __nv_bfloat16 g_A[(size_t)QDIM * KSPLIT];   // 6.3 MB
__device__ __align__(128) __nv_bfloat16 g_B[(size_t)NDIM * KSPLIT];   // 12.6 MB
__device__ __align__(128) float g_q2[QDIM];
__device__ __align__(128) float g_n2[NDIM];
__device__ __align__(128) float g_w[(size_t)QDIM * NDIM];             // 128 MB

// ---------------------------------------------------------------------------
// PTX helpers (sm_80-era features only — final target is plain sm_100)
// ---------------------------------------------------------------------------
__device__ __forceinline__ uint32_t smem_to_u32(const void* p) {
    uint32_t a;
    asm("{ .reg .u64 t; cvta.to.shared.u64 t, %1; cvt.u32.u64 %0, t; }"
        : "=r"(a) : "l"(p));
    return a;
}

__device__ __forceinline__ void cpasync16(uint32_t dst, const void* src) {
    asm volatile("cp.async.cg.shared.global [%0], [%1], 16;"
                 :: "r"(dst), "l"(src) : "memory");
}
__device__ __forceinline__ void cp_commit() {
    asm volatile("cp.async.commit_group;" ::: "memory");
}
template <int N> __device__ __forceinline__ void cp_wait() {
    asm volatile("cp.async.wait_group %0;" :: "n"(N) : "memory");
}

__device__ __forceinline__ void ldmatrix_x4(uint32_t* r, uint32_t addr) {
    asm volatile("ldmatrix.sync.aligned.m8n8.x4.shared.b16 {%0,%1,%2,%3}, [%4];"
                 : "=r"(r[0]), "=r"(r[1]), "=r"(r[2]), "=r"(r[3]) : "r"(addr));
}

__device__ __forceinline__ void mma_bf16(float* c, const uint32_t* a,
                                         const uint32_t* b) {
    asm volatile(
        "mma.sync.aligned.m16n8k16.row.col.f32.bf16.bf16.f32 "
        "{%0,%1,%2,%3}, {%4,%5,%6,%7}, {%8,%9}, {%0,%1,%2,%3};"
        : "+f"(c[0]), "+f"(c[1]), "+f"(c[2]), "+f"(c[3])
        : "r"(a[0]), "r"(a[1]), "r"(a[2]), "r"(a[3]), "r"(b[0]), "r"(b[1]));
}

// ---------------------------------------------------------------------------
// Kernel 1: fp32 row norms + split-bf16 operand build
// grid = QDIM + NDIM blocks, 64 threads
// ---------------------------------------------------------------------------
__global__ void prep_kernel(const float* __restrict__ query,
                            const float* __restrict__ neigh) {
    int row = blockIdx.x;
    bool isQ = row < QDIM;
    int r = isQ ? row : row - QDIM;
    const float* src = isQ ? query + (size_t)r * DDIM : neigh + (size_t)r * DDIM;
    __nv_bfloat16* dst = isQ ? g_A + (size_t)r * KSPLIT : g_B + (size_t)r * KSPLIT;

    int t = threadIdx.x;
    float4 v = ((const float4*)src)[t];
    float vv[4] = {v.x, v.y, v.z, v.w};
    float s = v.x * v.x + v.y * v.y + v.z * v.z + v.w * v.w;

    __nv_bfloat16 hi[4], lo[4];
#pragma unroll
    for (int i = 0; i < 4; ++i) {
        hi[i] = __float2bfloat16(vv[i]);
        lo[i] = __float2bfloat16(vv[i] - __bfloat162float(hi[i]));
    }
    int base = t * 4;
    __nv_bfloat162 h01(hi[0], hi[1]), h23(hi[2], hi[3]);
    __nv_bfloat162 l01(lo[0], lo[1]), l23(lo[2], lo[3]);
    __nv_bfloat162* d0 = (__nv_bfloat162*)(dst + base);
    __nv_bfloat162* d1 = (__nv_bfloat162*)(dst + 256 + base);
    __nv_bfloat162* d2 = (__nv_bfloat162*)(dst + 512 + base);
    if (isQ) {  // A'' = [hi | hi | lo]
        d0[0] = h01; d0[1] = h23;
        d1[0] = h01; d1[1] = h23;
        d2[0] = l01; d2[1] = l23;
    } else {    // B'' = [hi | lo | hi]
        d0[0] = h01; d0[1] = h23;
        d1[0] = l01; d1[1] = l23;
        d2[0] = h01; d2[1] = h23;
    }

#pragma unroll
    for (int off = 16; off > 0; off >>= 1)
        s += __shfl_xor_sync(0xffffffffu, s, off);
    __shared__ float sh[2];
    if ((t & 31) == 0) sh[t >> 5] = s;
    __syncthreads();
    if (t == 0) {
        float tot = sh[0] + sh[1];
        if (isQ) g_q2[r] = tot; else g_n2[r] = tot;
    }
}

// ---------------------------------------------------------------------------
// Kernel 2: HMMA bf16 GEMM (M=128,N=128,K=768) + fused epilogue -> g_w
// 256 threads, 8 warps as 4(M) x 2(N); warp tile 32x64
// smem: STAGES x (A 16KB + B 16KB), XOR-swizzled 16B units
// ---------------------------------------------------------------------------
#define STAGE_BYTES (BM * 128 + BN * 128)         // 32 KB
#define SMEM_DYN    (STAGES * STAGE_BYTES)        // 128 KB

__device__ __forceinline__ void load_tile(uint32_t abuf, uint32_t bbuf,
                                          int kt, int qbase, int nbase,
                                          int tid) {
    // tile rows of 64 bf16 = 128B = 8 x 16B units; 1024 units per operand
    const char* gA = (const char*)g_A + ((size_t)qbase * KSPLIT + (size_t)kt * BK) * 2;
    const char* gB = (const char*)g_B + ((size_t)nbase * KSPLIT + (size_t)kt * BK) * 2;
#pragma unroll
    for (int i = 0; i < 4; ++i) {
        int g = tid * 4 + i;         // 0..1023
        int r = g >> 3;              // row 0..127
        int ku = g & 7;              // 16B unit within row
        uint32_t so = (uint32_t)(r * 128 + ((ku ^ (r & 7)) << 4));
        const char* sa = gA + (size_t)r * (KSPLIT * 2) + (size_t)ku * 16;
        const char* sb = gB + (size_t)r * (KSPLIT * 2) + (size_t)ku * 16;
        cpasync16(abuf + so, sa);
        cpasync16(bbuf + so, sb);
    }
}

__global__ void __launch_bounds__(256, 1)
gemm_kernel(const float* __restrict__ gumbel) {
    extern __shared__ char smem_raw[];
    uint32_t sbase = smem_to_u32(smem_raw);

    int tid = threadIdx.x;
    int wid = tid >> 5;
    int l   = tid & 31;
    int warpm = wid & 3;         // 0..3 -> 32-row slab
    int warpn = wid >> 2;        // 0..1 -> 64-col slab

    int nbase = blockIdx.x * BN;
    int qbase = blockIdx.y * BM;

    uint32_t abuf[STAGES], bbuf[STAGES];
#pragma unroll
    for (int s = 0; s < STAGES; ++s) {
        abuf[s] = sbase + s * STAGE_BYTES;
        bbuf[s] = abuf[s] + BM * 128;
    }

    // prologue: tiles 0..2
#pragma unroll
    for (int c = 0; c < 3; ++c) {
        load_tile(abuf[c], bbuf[c], c, qbase, nbase, tid);
        cp_commit();
    }

    float acc[2][8][4];
#pragma unroll
    for (int mt = 0; mt < 2; ++mt)
#pragma unroll
        for (int nt = 0; nt < 8; ++nt)
#pragma unroll
            for (int i = 0; i < 4; ++i) acc[mt][nt][i] = 0.f;

    // precomputed ldmatrix lane address offsets (row, unit) patterns
    int a_lr = (l & 15);                      // A: row offset within 16-row tile
    int a_ku = (l >> 4);                      // A: +0/+1 unit
    int b_lr = ((l >> 4) << 3) + (l & 7);     // B: row offset within 16-row tile
    int b_ku = ((l >> 3) & 1);                // B: +0/+1 unit

#pragma unroll
    for (int kt = 0; kt < NKT; ++kt) {
        const int s = kt % STAGES;
        cp_wait<2>();
        __syncthreads();

        uint32_t aS = abuf[s], bS = bbuf[s];
#pragma unroll
        for (int ks = 0; ks < 4; ++ks) {       // k0 = ks*16
            int kb = ks * 2;                   // base 16B unit
            uint32_t afr[2][4];
#pragma unroll
            for (int mt = 0; mt < 2; ++mt) {
                int r = warpm * 32 + mt * 16 + a_lr;
                uint32_t addr = aS + r * 128 + (((kb + a_ku) ^ (r & 7)) << 4);
                ldmatrix_x4(afr[mt], addr);
            }
            uint32_t bfr[4][4];
#pragma unroll
            for (int bt = 0; bt < 4; ++bt) {
                int r = warpn * 64 + bt * 16 + b_lr;
                uint32_t addr = bS + r * 128 + (((kb + b_ku) ^ (r & 7)) << 4);
                ldmatrix_x4(bfr[bt], addr);
            }
#pragma unroll
            for (int mt = 0; mt < 2; ++mt)
#pragma unroll
                for (int nt = 0; nt < 8; ++nt)
                    mma_bf16(acc[mt][nt], afr[mt], &bfr[nt >> 1][(nt & 1) * 2]);
        }

        __syncthreads();
        if (kt + 3 < NKT)
            load_tile(abuf[(kt + 3) % STAGES], bbuf[(kt + 3) % STAGES],
                      kt + 3, qbase, nbase, tid);
        cp_commit();
    }
    cp_wait<0>();

    // Fused epilogue: w = gumbel - sqrt(max(q2 + n2 - 2*dot, 0))
    {
        int row0 = qbase + warpm * 32 + (l >> 2);
        int colb = nbase + warpn * 64 + (l & 3) * 2;
#pragma unroll
        for (int mt = 0; mt < 2; ++mt) {
            int rA = row0 + mt * 16;
            int rB = rA + 8;
            float q2a = __ldg(&g_q2[rA]);
            float q2b = __ldg(&g_q2[rB]);
            const float* gAraw = gumbel + (size_t)rA * NDIM;
            const float* gBraw = gumbel + (size_t)rB * NDIM;
            float* wA = g_w + (size_t)rA * NDIM;
            float* wB = g_w + (size_t)rB * NDIM;
#pragma unroll
            for (int nt = 0; nt < 8; ++nt) {
                int col = colb + nt * 8;
                float n2a = __ldg(&g_n2[col]);
                float n2b = __ldg(&g_n2[col + 1]);
                float2 ga = *(const float2*)(gAraw + col);
                float2 gb = *(const float2*)(gBraw + col);
                float2 oa, ob;
                oa.x = ga.x - sqrtf(fmaxf(fmaf(-2.f, acc[mt][nt][0], q2a + n2a), 0.f));
                oa.y = ga.y - sqrtf(fmaxf(fmaf(-2.f, acc[mt][nt][1], q2a + n2b), 0.f));
                ob.x = gb.x - sqrtf(fmaxf(fmaf(-2.f, acc[mt][nt][2], q2b + n2a), 0.f));
                ob.y = gb.y - sqrtf(fmaxf(fmaf(-2.f, acc[mt][nt][3], q2b + n2b), 0.f));
                *(float2*)(wA + col) = oa;
                *(float2*)(wB + col) = ob;
            }
        }
    }
}

// ---------------------------------------------------------------------------
// Kernel 3: iterative relaxed top-k; one block per query row
//   e = exp(w - m); 10x { p = e/sum; khot += p; e *= max(1-p, tiny) }
// ---------------------------------------------------------------------------
__global__ void __launch_bounds__(512)
iter_kernel(float* __restrict__ out) {
    __shared__ float sred[16];
    __shared__ float sbc;

    int t = threadIdx.x;
    int w = t >> 5, l = t & 31;
    const float4* wrow = (const float4*)(g_w + (size_t)blockIdx.x * NDIM);
    float4* orow = (float4*)(out + (size_t)blockIdx.x * NDIM);

    float4 v[4];
    float mx = -3.4e38f;
#pragma unroll
    for (int i = 0; i < 4; ++i) {
        v[i] = wrow[i * 512 + t];
        mx = fmaxf(mx, fmaxf(fmaxf(v[i].x, v[i].y), fmaxf(v[i].z, v[i].w)));
    }
#pragma unroll
    for (int o = 16; o > 0; o >>= 1)
        mx = fmaxf(mx, __shfl_xor_sync(0xffffffffu, mx, o));
    if (l == 0) sred[w] = mx;
    __syncthreads();
    if (w == 0) {
        float m2 = sred[l & 15];
#pragma unroll
        for (int o = 8; o > 0; o >>= 1)
            m2 = fmaxf(m2, __shfl_xor_sync(0xffffffffu, m2, o));
        if (l == 0) sbc = m2;
    }
    __syncthreads();
    float M = sbc;

    float e[16], kh[16];
#pragma unroll
    for (int i = 0; i < 4; ++i) {
        e[i * 4 + 0] = __expf(v[i].x - M);
        e[i * 4 + 1] = __expf(v[i].y - M);
        e[i * 4 + 2] = __expf(v[i].z - M);
        e[i * 4 + 3] = __expf(v[i].w - M);
    }
#pragma unroll
    for (int j = 0; j < 16; ++j) kh[j] = 0.f;

#pragma unroll
    for (int it = 0; it < NITER; ++it) {
        float s = 0.f;
#pragma unroll
        for (int j = 0; j < 16; ++j) s += e[j];
#pragma unroll
        for (int o = 16; o > 0; o >>= 1)
            s += __shfl_xor_sync(0xffffffffu, s, o);
        if (l == 0) sred[w] = s;
        __syncthreads();
        if (w == 0) {
            float s2 = sred[l & 15];
#pragma unroll
            for (int o = 8; o > 0; o >>= 1)
                s2 += __shfl_xor_sync(0xffffffffu, s2, o);
            if (l == 0) sbc = s2;
        }
        __syncthreads();
        float inv = 1.0f / sbc;
#pragma unroll
        for (int j = 0; j < 16; ++j) {
            float p = e[j] * inv;
            kh[j] += p;
            e[j] *= fmaxf(1.0f - p, 1.1754944e-38f);
        }
        if (it + 1 < NITER) __syncthreads();
    }

#pragma unroll
    for (int i = 0; i < 4; ++i) {
        float4 o4;
        o4.x = kh[i * 4 + 0];
        o4.y = kh[i * 4 + 1];
        o4.z = kh[i * 4 + 2];
        o4.w = kh[i * 4 + 3];
        orow[i * 512 + t] = o4;
    }
}

// ---------------------------------------------------------------------------
// Launch
// ---------------------------------------------------------------------------
extern "C" void kernel_launch(void* const* d_in, const int* in_sizes, int n_in,
                              void* d_out, int out_size) {
    const float* query  = (const float*)d_in[0];   // [4096, 256]
    const float* neigh  = (const float*)d_in[1];   // [1, 8192, 256]
    const float* gumbel = (const float*)d_in[2];   // [4096, 8192]
    float* out = (float*)d_out;                    // [4096, 8192]

    prep_kernel<<<QDIM + NDIM, 64>>>(query, neigh);

    static bool attr_done = false;
    if (!attr_done) {
        cudaFuncSetAttribute(gemm_kernel,
                             cudaFuncAttributeMaxDynamicSharedMemorySize,
                             SMEM_DYN);
        attr_done = true;
    }
    dim3 grid(NDIM / BN, QDIM / BM);
    gemm_kernel<<<grid, 256, SMEM_DYN>>>(gumbel);

    iter_kernel<<<QDIM, 512>>>(out);
}